// round 15
// baseline (speedup 1.0000x reference)
#include <cuda_runtime.h>
#include <cuda_fp16.h>
#include <cstdint>

// ---------------- constants ----------------
#define IMG   224
#define BATCH 32
#define NPIX1 12544
#define NPIX2 3136
#define N1F   401408.0f
#define N2F   100352.0f

// conv1 smem geometry (fp16x2: Ah, Al, B)
#define RSTRIDE 80
#define ATERM   10240
#define BOFF    20480
#define STAGE1  25600
#define DYN1    51200

// conv2 geometry: two-row CTA, single-term A (8KB) + B (8KB), 5 stages
#define C2_BOFF  8192
#define C2_STAGE 16384
#define C2_NSTG  5
#define C2_DYN   (C2_NSTG*C2_STAGE)   // 81920

// padded activation plane
#define PSTRIDE 64
#define PPLANE  3712
#define GUARD   128

// packed conv1 output
#define NPMAX 5376
#define POOL_DYN (4*NPMAX*4)          // 86016

struct Win { int ti, li, to, lo, oh, ow, fh, fw, base; };
struct WinTab { Win w[28]; };

// ---------------- scratch ----------------
__device__ __half g_in16[BATCH*3*IMG*IMG];
__device__ __half g_fpk[BATCH*128*NPMAX];
__device__ __half g_hp[GUARD + BATCH*128*PPLANE + GUARD];
__device__ __half g_hs[GUARD + BATCH*128*PPLANE + GUARD];
__device__ __half g_hm[GUARD + BATCH*128*PPLANE + GUARD];
__device__ __half g_w1h[128*160], g_w1l[128*160];
__device__ __half g_w2h[128*1152];
__device__ unsigned short g_map16[NPIX1];
__device__ int   g_wgt[NPMAX];
__device__ int2  g_pc[NPMAX];
__device__ float g_sum1[128], g_sq1[128], g_sum2[128], g_sq2[128];

// ---------------- helpers ----------------
__device__ __forceinline__ uint32_t smem_u32(const void* p) {
    uint32_t a;
    asm("{ .reg .u64 t; cvta.to.shared.u64 t, %1; cvt.u32.u64 %0, t; }" : "=r"(a) : "l"(p));
    return a;
}
__device__ __forceinline__ void ldsm4(uint32_t addr, uint32_t* r) {
    asm volatile("ldmatrix.sync.aligned.m8n8.x4.shared.b16 {%0,%1,%2,%3}, [%4];"
        : "=r"(r[0]), "=r"(r[1]), "=r"(r[2]), "=r"(r[3]) : "r"(addr));
}
__device__ __forceinline__ void ldsm4t(uint32_t addr, uint32_t* r) {
    asm volatile("ldmatrix.sync.aligned.m8n8.x4.trans.shared.b16 {%0,%1,%2,%3}, [%4];"
        : "=r"(r[0]), "=r"(r[1]), "=r"(r[2]), "=r"(r[3]) : "r"(addr));
}
__device__ __forceinline__ void mma16816(float* c, const uint32_t* a, const uint32_t* b) {
    asm volatile("mma.sync.aligned.m16n8k16.row.col.f32.f16.f16.f32 "
        "{%0,%1,%2,%3}, {%4,%5,%6,%7}, {%8,%9}, {%0,%1,%2,%3};"
        : "+f"(c[0]), "+f"(c[1]), "+f"(c[2]), "+f"(c[3])
        : "r"(a[0]), "r"(a[1]), "r"(a[2]), "r"(a[3]), "r"(b[0]), "r"(b[1]));
}
#define CP16(dst, src) \
    asm volatile("cp.async.cg.shared.global [%0], [%1], 16;" :: "r"(dst), "l"(src) : "memory")
#define CPCOMMIT() asm volatile("cp.async.commit_group;" ::: "memory")
#define CPWAIT(n)  asm volatile("cp.async.wait_group %0;" :: "n"(n) : "memory")

#define CPA(WH, WL, KDIM, s, buf, STAGE) do { \
    _Pragma("unroll") for (int i = 0; i < 4; i++) { \
        int id = tid + i*256, term = id >> 9, rem = id & 511, row = rem >> 2, c = rem & 3; \
        const __half* src = (term ? (WL) : (WH)) + row*(KDIM) + (s)*32 + c*8; \
        uint32_t dst = sb + (buf)*(STAGE) + term*ATERM + row*RSTRIDE + c*16; \
        CP16(dst, src); } \
    CPCOMMIT(); } while (0)

// ---------------- fused setup ----------------
#define SU_W 576
#define SU_P 4704
#define SU_M 49
#define SU_I 21
__global__ void k_setup(const float4* __restrict__ inp,
                        const float* __restrict__ w1, const float* __restrict__ w2,
                        WinTab tab) {
    int b = blockIdx.x, tid = threadIdx.x;
    if (b < SU_W) {
        int t = b*256 + tid;
        if (t < 128) { g_sum1[t] = 0.f; g_sq1[t] = 0.f; g_sum2[t] = 0.f; g_sq2[t] = 0.f; }
        if (t < 128*160) {
            int oc = t / 160, k = t - oc*160;
            float v = (k < 147) ? w1[oc*147 + k] : 0.f;
            __half h = __float2half_rn(v);
            g_w1h[t] = h;
            g_w1l[t] = __float2half_rn(v - __half2float(h));
        }
        if (t < 128*1152) g_w2h[t] = __float2half_rn(w2[t]);
    } else if (b < SU_W + SU_P) {
        int i = (b - SU_W)*256 + tid;
        float4 v = inp[i];
        __half2 a = __floats2half2_rn(v.x, v.y);
        __half2 c = __floats2half2_rn(v.z, v.w);
        *(uint2*)(g_in16 + i*4) = make_uint2(*(uint32_t*)&a, *(uint32_t*)&c);
    } else if (b < SU_W + SU_P + SU_M) {
        int pix = (b - SU_W - SU_P)*256 + tid;
        int y = pix / 112, x = pix - y*112;
        int bi = y >> 3, bj = x >> 3;
        int sS = min(min(bi, bj), min(13 - bi, 13 - bj));
        int b2 = 8 * (sS + 1), c2v = 112 - b2;
        int w = (y < b2 && x < c2v) ? 0 : (x < b2 ? 1 : (y >= c2v ? 2 : 3));
        Win W = tab.w[sS*4 + w];
        int fy = ((y - W.to) * W.fh) / W.oh;
        int fx = ((x - W.lo) * W.fw) / W.ow;
        g_map16[pix] = (unsigned short)(W.base + fy * W.fw + fx);
    } else {
        int id = (b - SU_W - SU_P - SU_M)*256 + tid;
        int si = 0;
        #pragma unroll
        for (int i = 1; i < 28; i++) if (id >= tab.w[i].base) si = i;
        Win W = tab.w[si];
        int off = id - W.base;
        if (off < W.fh * W.fw) {
            int fy = off / W.fw, fx = off - fy*W.fw;
            int cy = ((fy+1)*W.oh + W.fh - 1)/W.fh - (fy*W.oh + W.fh - 1)/W.fh;
            int cx = ((fx+1)*W.ow + W.fw - 1)/W.fw - (fx*W.ow + W.fw - 1)/W.fw;
            g_wgt[id] = cy * cx;
            g_pc[id] = make_int2(W.ti + 2*fy - 3, W.li + 2*fx - 3);
        } else {
            g_wgt[id] = 0;
            g_pc[id] = make_int2(0, 0);
        }
    }
}

// ---------------- conv1: fp16x2 over packed pixels, fp16 gather ----------------
__global__ void __launch_bounds__(256, 3) k_conv1m() {
    extern __shared__ __align__(128) char dsm[];
    __shared__ int t_c[160];
    __shared__ signed char t_ky[160], t_kx[160];
    __shared__ float s_red[256];
    __shared__ float s_wgt[64];

    int tid = threadIdx.x, lane = tid & 31, wid = tid >> 5;
    int warp_m = wid & 3, warp_n = wid >> 2;

    if (tid < 160) {
        int k = tid;
        if (k < 147) {
            int c = k / 49, r = k - c*49, ky = r / 7, kx = r - ky*7;
            t_c[k] = c * 50176; t_ky[k] = (signed char)ky; t_kx[k] = (signed char)kx;
        } else { t_c[k] = -1; t_ky[k] = 0; t_kx[k] = 0; }
    }
    s_red[tid] = 0.f;

    int img = blockIdx.y;
    int pixbase = blockIdx.x * 64;
    if (tid < 64) s_wgt[tid] = (float)g_wgt[pixbase + tid];
    __syncthreads();

    int pix = pixbase + (tid >> 2);
    int kq = tid & 3;
    int2 pcv = g_pc[pix];
    int iy0 = pcv.x, ix0 = pcv.y;
    const __half* ibase = g_in16 + img * 150528;

    uint32_t sb = smem_u32(dsm);
    uint32_t Aln = (lane & 15)*RSTRIDE + (lane >> 4)*16;
    uint32_t Bln = ((lane >> 4)*8 + (lane & 7))*RSTRIDE + ((lane >> 3) & 1)*16;
    uint32_t bsts = (tid >> 2)*RSTRIDE + kq*16;

    uint32_t hw[4];
    #define C1_LDGB(s) do { int kb = (s)*32 + kq*8; \
        unsigned short bu[8]; \
        _Pragma("unroll") for (int j = 0; j < 8; j++) { \
            int k = kb + j; \
            int iy = iy0 + t_ky[k], ix = ix0 + t_kx[k]; \
            bool v = (t_c[k] >= 0) && ((unsigned)iy < 224u) && ((unsigned)ix < 224u); \
            bu[j] = v ? __half_as_ushort(__ldg(ibase + t_c[k] + iy*224 + ix)) : (unsigned short)0; } \
        _Pragma("unroll") for (int j = 0; j < 4; j++) \
            hw[j] = (uint32_t)bu[2*j] | ((uint32_t)bu[2*j+1] << 16); } while (0)
    #define C1_STSB(buf) do { \
        *(uint4*)(dsm + (buf)*STAGE1 + BOFF + bsts) = make_uint4(hw[0], hw[1], hw[2], hw[3]); } while (0)

    float acc[2][4][4];
    #pragma unroll
    for (int a = 0; a < 2; a++)
        #pragma unroll
        for (int b = 0; b < 4; b++)
            #pragma unroll
            for (int c = 0; c < 4; c++) acc[a][b][c] = 0.f;

    CPA(g_w1h, g_w1l, 160, 0, 0, STAGE1);
    CPA(g_w1h, g_w1l, 160, 1, 1, STAGE1);
    C1_LDGB(0);
    CPWAIT(1);
    C1_STSB(0);
    __syncthreads();

    for (int s = 0; s < 5; s++) {
        int buf = s & 1;
        if (s < 4) C1_LDGB(s + 1);
        {
            uint32_t Ab = sb + buf*STAGE1 + warp_m*(32*RSTRIDE);
            uint32_t Bb = sb + buf*STAGE1 + BOFF + warp_n*(32*RSTRIDE);
            #pragma unroll
            for (int h = 0; h < 2; h++) {
                uint32_t ab = Ab + h*32 + Aln;
                uint32_t bb = Bb + h*32 + Bln;
                uint32_t am[2][4], bq[4][2], t[4];
                ldsm4(bb, t); bq[0][0]=t[0]; bq[0][1]=t[1]; bq[1][0]=t[2]; bq[1][1]=t[3];
                ldsm4(bb + 16*RSTRIDE, t); bq[2][0]=t[0]; bq[2][1]=t[1]; bq[3][0]=t[2]; bq[3][1]=t[3];
                ldsm4(ab, am[0]); ldsm4(ab + 16*RSTRIDE, am[1]);
                #pragma unroll
                for (int mt = 0; mt < 2; mt++)
                    #pragma unroll
                    for (int nt = 0; nt < 4; nt++) mma16816(acc[mt][nt], am[mt], bq[nt]);
                ldsm4(ab + ATERM, am[0]); ldsm4(ab + ATERM + 16*RSTRIDE, am[1]);
                #pragma unroll
                for (int mt = 0; mt < 2; mt++)
                    #pragma unroll
                    for (int nt = 0; nt < 4; nt++) mma16816(acc[mt][nt], am[mt], bq[nt]);
            }
        }
        if (s < 4) {
            CPWAIT(0);
            C1_STSB(buf ^ 1);
            __syncthreads();
            if (s + 2 < 5) CPA(g_w1h, g_w1l, 160, s + 2, buf, STAGE1);
        }
    }

    int g = lane >> 2, cp = (lane & 3) * 2;
    #pragma unroll
    for (int mt = 0; mt < 2; mt++) {
        #pragma unroll
        for (int hh = 0; hh < 2; hh++) {
            int oc = warp_m*32 + mt*16 + hh*8 + g;
            float sv = 0.f, qv = 0.f;
            __half* obase = g_fpk + (size_t)(img*128 + oc)*NPMAX + pixbase;
            #pragma unroll
            for (int nt = 0; nt < 4; nt++) {
                float c0 = acc[mt][nt][hh*2], c1 = acc[mt][nt][hh*2 + 1];
                int pxl = warp_n*32 + nt*8 + cp;
                *(__half2*)(obase + pxl) = __floats2half2_rn(c0, c1);
                float w0 = s_wgt[pxl], w1 = s_wgt[pxl + 1];
                sv += w0*c0 + w1*c1; qv += w0*c0*c0 + w1*c1*c1;
            }
            atomicAdd(&s_red[oc], sv);
            atomicAdd(&s_red[128 + oc], qv);
        }
    }
    __syncthreads();
    if (tid < 128) {
        atomicAdd(&g_sum1[tid], s_red[tid]);
        atomicAdd(&g_sq1[tid],  s_red[128 + tid]);
    }
}

// ---------------- BN1 + ReLU + maxpool v5: half2 channel pairs, 8 planes/block ----------------
__global__ void __launch_bounds__(256) k_pool(const float* __restrict__ gamma,
                                              const float* __restrict__ beta) {
    extern __shared__ __half2 sp2[];   // 4 pairs * NPMAX half2 = 86 KB
    int tid = threadIdx.x;
    int ncb0 = blockIdx.x * 8;

    // load + interleave 4 channel pairs
    #pragma unroll
    for (int q = 0; q < 4; q++) {
        const uint4* a4 = (const uint4*)(g_fpk + (size_t)(ncb0 + 2*q) * NPMAX);
        const uint4* b4 = (const uint4*)(g_fpk + (size_t)(ncb0 + 2*q + 1) * NPMAX);
        uint2* dst = (uint2*)(sp2 + q*NPMAX);
        for (int i = tid; i < NPMAX/8; i += 256) {
            uint4 a = __ldg(a4 + i), b = __ldg(b4 + i);
            dst[i*4+0] = make_uint2(__byte_perm(a.x, b.x, 0x5410), __byte_perm(a.x, b.x, 0x7632));
            dst[i*4+1] = make_uint2(__byte_perm(a.y, b.y, 0x5410), __byte_perm(a.y, b.y, 0x7632));
            dst[i*4+2] = make_uint2(__byte_perm(a.z, b.z, 0x5410), __byte_perm(a.z, b.z, 0x7632));
            dst[i*4+3] = make_uint2(__byte_perm(a.w, b.w, 0x5410), __byte_perm(a.w, b.w, 0x7632));
        }
    }
    __syncthreads();

    int w = tid >> 5, lane = tid & 31;
    int q = w >> 1, wp = w & 1;
    int ncb = ncb0 + 2*q;              // low channel of pair
    int c0 = ncb & 127;

    float mean0 = g_sum1[c0] * (1.f / N1F);
    float var0  = g_sq1[c0]  * (1.f / N1F) - mean0*mean0;
    float a0 = __ldg(gamma + c0) * rsqrtf(var0 + 1e-5f);
    float b0 = __ldg(beta + c0) - a0 * mean0;
    float mean1 = g_sum1[c0+1] * (1.f / N1F);
    float var1  = g_sq1[c0+1]  * (1.f / N1F) - mean1*mean1;
    float a1 = __ldg(gamma + c0+1) * rsqrtf(var1 + 1e-5f);
    float b1 = __ldg(beta + c0+1) - a1 * mean1;
    bool pos0 = (a0 >= 0.f), pos1 = (a1 >= 0.f);

    const __half2* sp = sp2 + q*NPMAX;

    int x = 28*wp + lane;              // output column (valid lane<28)
    bool bnd = lane >= 28;
    int ce = max(56*wp - 1, 0);
    int cc = bnd ? (ce & ~1) : 2*x;

    const __half2 NEG2 = __halves2half2(__ushort_as_half(0xFC00), __ushort_as_half(0xFC00));
    const __half2 POS2 = __halves2half2(__ushort_as_half(0x7C00), __ushort_as_half(0x7C00));
    __half2 cvx0 = NEG2, cvn0 = POS2, cvx1 = NEG2, cvn1 = POS2;

    __half* hpO = g_hp + GUARD + (size_t)ncb * PPLANE;
    __half* hsO = g_hs + GUARD + (size_t)ncb * PPLANE;
    __half* hmO = g_hm + GUARD + (size_t)ncb * PPLANE;

    int srcl = lane ? lane - 1 : 28;

    for (int y = 0; y < 56; y++) {
        const unsigned short* m0 = g_map16 + (2*y)*112;
        uint32_t u0 = __ldg((const uint32_t*)(m0 + cc));
        uint32_t u1 = __ldg((const uint32_t*)(m0 + 112 + cc));
        __half2 va0 = sp[u0 & 0xffff], va1 = sp[u0 >> 16];
        __half2 vb0 = sp[u1 & 0xffff], vb1 = sp[u1 >> 16];
        __half2 mx0 = __hmax2(__hmax2(cvx0, va0), vb0);
        __half2 mn0 = __hmin2(__hmin2(cvn0, va0), vb0);
        __half2 mx1 = __hmax2(__hmax2(cvx1, va1), vb1);
        __half2 mn1 = __hmin2(__hmin2(cvn1, va1), vb1);
        cvx0 = vb0; cvn0 = vb0; cvx1 = vb1; cvn1 = vb1;

        __half2 sx2 = mx1, sn2 = mn1;
        if (bnd && !(ce & 1)) { sx2 = mx0; sn2 = mn0; }
        uint32_t pvx = __shfl_sync(0xFFFFFFFFu, *(uint32_t*)&sx2, srcl);
        uint32_t pvn = __shfl_sync(0xFFFFFFFFu, *(uint32_t*)&sn2, srcl);

        if (lane < 28) {
            __half2 px = *(__half2*)&pvx, pn = *(__half2*)&pvn;
            __half2 MX = __hmax2(__hmax2(px, mx0), mx1);
            __half2 MN = __hmin2(__hmin2(pn, mn0), mn1);
            float v0 = __half2float(pos0 ? __low2half(MX)  : __low2half(MN));
            float v1 = __half2float(pos1 ? __high2half(MX) : __high2half(MN));
            __half h0 = __float2half_rn(fmaxf(fmaf(a0, v0, b0), 0.f));
            __half h1 = __float2half_rn(fmaxf(fmaf(a1, v1, b1), 0.f));
            int p = (y + 1)*64 + x;
            hpO[p] = h0; hsO[p - 1] = h0; hmO[p + 1] = h0;
            hpO[p + PPLANE] = h1; hsO[p + PPLANE - 1] = h1; hmO[p + PPLANE + 1] = h1;
        }
    }
}

// ---------------- conv2: two-row CTA, single-term A, 16B cp.async, 5 stages ----------------
__global__ void __launch_bounds__(256, 2) k_conv2m(float* __restrict__ out) {
    extern __shared__ __align__(128) char dsm[];
    __shared__ int t_bo[1152];
    __shared__ float s_red[256];

    int tid = threadIdx.x, lane = tid & 31, wid = tid >> 5;
    int warp_m = wid & 3, warp_n = wid >> 2;

    for (int k = tid; k < 1152; k += 256) {
        int ic = k / 9, r = k - ic*9;
        int dy = r/3 - 1, dx = r - (r/3)*3 - 1;
        t_bo[k] = ((ic*PPLANE + dy*64 + 64) << 2) | (dx + 1);
    }
    s_red[tid] = 0.f;
    __syncthreads();

    int img = blockIdx.x / 28;
    int t2  = blockIdx.x - img*28;
    int yp0 = 2*t2 + 1;
    size_t ibase = (size_t)img * 128 * PPLANE;
    const __half* HP = g_hp + GUARD;
    const __half* HS = g_hs + GUARD;
    const __half* HM = g_hm + GUARD;

    uint32_t sb = smem_u32(dsm);

    #define C2_CPA(s, buf) do { \
        _Pragma("unroll") for (int i = 0; i < 2; i++) { \
            int id = tid + i*256, row = id >> 2, c = id & 3; \
            const __half* src = g_w2h + row*1152 + (s)*32 + c*8; \
            uint32_t dst = sb + (buf)*C2_STAGE + row*64 + (((c ^ ((row>>1)&3)) << 4)); \
            CP16(dst, src); } } while (0)
    #define C2_CPB(s, buf) do { \
        _Pragma("unroll") for (int i = 0; i < 2; i++) { \
            int id = tid + i*256, krow = id >> 4, G = id & 15; \
            int p = t_bo[(s)*32 + krow]; \
            int sel = p & 3; \
            const __half* base = (sel == 0) ? HM : ((sel == 1) ? HP : HS); \
            int r = G >> 3, gx = G & 7; \
            const __half* src = base + ibase + ((p >> 2) - 64) + (yp0 + r)*64 + gx*8; \
            uint32_t dst = sb + (buf)*C2_STAGE + C2_BOFF + krow*256 + (((G ^ (krow & 7)) << 4)); \
            CP16(dst, src); } } while (0)

    uint32_t arow = warp_m*32 + (lane & 15);
    uint32_t aswz = (arow >> 1) & 3;
    uint32_t arb  = arow * 64;
    uint32_t acol = lane >> 4;
    uint32_t brow = ((lane >> 3) & 1)*8 + (lane & 7);
    uint32_t bswz = lane & 7;
    uint32_t bg0  = warp_n*8 + (lane >> 4);

    float acc[2][8][4];
    #pragma unroll
    for (int a = 0; a < 2; a++)
        #pragma unroll
        for (int b = 0; b < 8; b++)
            #pragma unroll
            for (int c = 0; c < 4; c++) acc[a][b][c] = 0.f;

    C2_CPA(0, 0); C2_CPB(0, 0); CPCOMMIT();
    C2_CPA(1, 1); C2_CPB(1, 1); CPCOMMIT();
    C2_CPA(2, 2); C2_CPB(2, 2); CPCOMMIT();
    C2_CPA(3, 3); C2_CPB(3, 3); CPCOMMIT();

    for (int s = 0; s < 36; s++) {
        CPWAIT(3);
        __syncthreads();
        int nb = (s + 4) % C2_NSTG;
        if (s + 4 < 36) { C2_CPA(s + 4, nb); C2_CPB(s + 4, nb); }
        CPCOMMIT();

        uint32_t bufb = sb + (s % C2_NSTG) * C2_STAGE;
        #pragma unroll
        for (int h = 0; h < 2; h++) {
            uint32_t t[4];
            uint32_t bq[8][2];
            uint32_t bbase = bufb + C2_BOFF + (h*16 + brow)*256;
            #pragma unroll
            for (int j = 0; j < 4; j++) {
                ldsm4t(bbase + (((bg0 + 2*j) ^ bswz) << 4), t);
                bq[2*j][0]   = t[0]; bq[2*j][1]   = t[1];
                bq[2*j+1][0] = t[2]; bq[2*j+1][1] = t[3];
            }
            uint32_t ac = (((h*2) + acol) ^ aswz) << 4;
            uint32_t am[2][4];
            ldsm4(bufb + arb + ac, am[0]);
            ldsm4(bufb + arb + 1024 + ac, am[1]);
            #pragma unroll
            for (int mt = 0; mt < 2; mt++)
                #pragma unroll
                for (int nt = 0; nt < 8; nt++) mma16816(acc[mt][nt], am[mt], bq[nt]);
        }
    }

    int g = lane >> 2, cp = (lane & 3) * 2;
    int yo = 2*t2 + warp_n;
    #pragma unroll
    for (int mt = 0; mt < 2; mt++) {
        #pragma unroll
        for (int hh = 0; hh < 2; hh++) {
            int oc = warp_m*32 + mt*16 + hh*8 + g;
            float sv = 0.f, qv = 0.f;
            float* obase = out + (size_t)(img*128 + oc)*NPIX2 + yo*56;
            #pragma unroll
            for (int nt = 0; nt < 8; nt++) {
                float c0 = acc[mt][nt][hh*2], c1 = acc[mt][nt][hh*2 + 1];
                int x = nt*8 + cp;
                if (x <= 55) { obase[x] = c0; sv += c0; qv += c0*c0; }
                if (x + 1 <= 55) { obase[x + 1] = c1; sv += c1; qv += c1*c1; }
            }
            atomicAdd(&s_red[oc], sv);
            atomicAdd(&s_red[128 + oc], qv);
        }
    }
    __syncthreads();
    if (tid < 128) {
        atomicAdd(&g_sum2[tid], s_red[tid]);
        atomicAdd(&g_sq2[tid],  s_red[128 + tid]);
    }
}

// ---------------- BN2 + ReLU in place (float4) ----------------
__global__ void k_bn2(float4* __restrict__ out,
                      const float* __restrict__ gamma, const float* __restrict__ beta) {
    int i = blockIdx.x * 256 + threadIdx.x;
    if (i >= BATCH * 128 * (NPIX2/4)) return;
    int c = (i / (NPIX2/4)) & 127;
    float mean = g_sum2[c] * (1.f / N2F);
    float var  = g_sq2[c]  * (1.f / N2F) - mean * mean;
    float a = __ldg(gamma + c) * rsqrtf(var + 1e-5f);
    float b = __ldg(beta + c) - a * mean;
    float4 v = out[i];
    v.x = fmaxf(fmaf(a, v.x, b), 0.f);
    v.y = fmaxf(fmaf(a, v.y, b), 0.f);
    v.z = fmaxf(fmaf(a, v.z, b), 0.f);
    v.w = fmaxf(fmaf(a, v.w, b), 0.f);
    out[i] = v;
}

// ---------------- launch ----------------
extern "C" void kernel_launch(void* const* d_in, const int* in_sizes, int n_in,
                              void* d_out, int out_size) {
    const float* inp = (const float*)d_in[0];
    const float* w1  = (const float*)d_in[1];
    const float* g1  = (const float*)d_in[2];
    const float* b1  = (const float*)d_in[3];
    const float* w2  = (const float*)d_in[4];
    const float* g2  = (const float*)d_in[5];
    const float* b2  = (const float*)d_in[6];
    float* out = (float*)d_out;

    WinTab tab;
    int np = 0;
    for (int s = 0; s < 7; s++) {
        int a = 16*s, b = a + 16, c = 224 - b, d = 224 - a;
        float scale = (float)(2.0 - (double)s / 6.0);
        for (int w = 0; w < 4; w++) {
            int t, l, bt, r;
            if      (w == 0) { t = a; l = a; bt = b; r = c; }
            else if (w == 1) { t = b; l = a; bt = d; r = b; }
            else if (w == 2) { t = c; l = b; bt = d; r = d; }
            else             { t = a; l = c; bt = c; r = d; }
            Win& W = tab.w[s*4 + w];
            W.ti = (int)((float)(t  + 6) / scale) - 3;
            W.li = (int)((float)(l  + 6) / scale) - 3;
            int bi = (int)((float)(bt + 6) / scale) + 3;
            int ri = (int)((float)(r  + 6) / scale) + 3;
            W.to = t >> 1; W.lo = l >> 1;
            W.oh = (bt >> 1) - W.to; W.ow = (r >> 1) - W.lo;
            W.fh = (bi - W.ti - 7) / 2 + 1;
            W.fw = (ri - W.li - 7) / 2 + 1;
            W.base = np;
            np += W.fh * W.fw;
        }
    }
    int tpi = (np + 63) / 64;

    cudaFuncSetAttribute(k_conv1m, cudaFuncAttributeMaxDynamicSharedMemorySize, DYN1);
    cudaFuncSetAttribute(k_conv2m, cudaFuncAttributeMaxDynamicSharedMemorySize, C2_DYN);
    cudaFuncSetAttribute(k_pool,   cudaFuncAttributeMaxDynamicSharedMemorySize, POOL_DYN);

    k_setup<<<SU_W + SU_P + SU_M + SU_I, 256>>>((const float4*)inp, w1, w2, tab);
    k_conv1m<<<dim3(tpi, BATCH), 256, DYN1>>>();
    k_pool<<<BATCH*16, 256, POOL_DYN>>>(g1, b1);
    k_conv2m<<<BATCH*28, 256, C2_DYN>>>(out);
    k_bn2<<<(BATCH*128*(NPIX2/4) + 255) / 256, 256>>>((float4*)out, g2, b2);
}

// round 16
// speedup vs baseline: 1.0343x; 1.0343x over previous
#include <cuda_runtime.h>
#include <cuda_fp16.h>
#include <cstdint>

// ---------------- constants ----------------
#define IMG   224
#define BATCH 32
#define NPIX1 12544
#define NPIX2 3136
#define N1F   401408.0f
#define N2F   100352.0f

// conv1 smem geometry (fp16x2: Ah, Al, B)
#define RSTRIDE 80
#define ATERM   10240
#define BOFF    20480
#define STAGE1  25600
#define DYN1    51200

// conv2 geometry: two-row CTA, single-term A (8KB) + B (8KB), 4 stages
#define C2_BOFF  8192
#define C2_STAGE 16384
#define C2_DYN   (4*C2_STAGE)

// padded activation plane
#define PSTRIDE 64
#define PPLANE  3712
#define GUARD   128

// packed conv1 output
#define NPMAX 5376

struct Win { int ti, li, to, lo, oh, ow, fh, fw, base; };
struct WinTab { Win w[28]; };

// ---------------- scratch ----------------
__device__ __half g_in16[BATCH*3*IMG*IMG];
__device__ __half g_fpk[BATCH*128*NPMAX];
__device__ __half g_hp[GUARD + BATCH*128*PPLANE + GUARD];
__device__ __half g_hs[GUARD + BATCH*128*PPLANE + GUARD];
__device__ __half g_hm[GUARD + BATCH*128*PPLANE + GUARD];
__device__ __half g_w1h[128*160], g_w1l[128*160];
__device__ __half g_w2h[128*1152];
__device__ unsigned short g_map16[NPIX1];
__device__ int   g_wgt[NPMAX];
__device__ int2  g_pc[NPMAX];
__device__ float g_sum1[128], g_sq1[128], g_sum2[128], g_sq2[128];

// ---------------- helpers ----------------
__device__ __forceinline__ uint32_t smem_u32(const void* p) {
    uint32_t a;
    asm("{ .reg .u64 t; cvta.to.shared.u64 t, %1; cvt.u32.u64 %0, t; }" : "=r"(a) : "l"(p));
    return a;
}
__device__ __forceinline__ void ldsm4(uint32_t addr, uint32_t* r) {
    asm volatile("ldmatrix.sync.aligned.m8n8.x4.shared.b16 {%0,%1,%2,%3}, [%4];"
        : "=r"(r[0]), "=r"(r[1]), "=r"(r[2]), "=r"(r[3]) : "r"(addr));
}
__device__ __forceinline__ void ldsm4t(uint32_t addr, uint32_t* r) {
    asm volatile("ldmatrix.sync.aligned.m8n8.x4.trans.shared.b16 {%0,%1,%2,%3}, [%4];"
        : "=r"(r[0]), "=r"(r[1]), "=r"(r[2]), "=r"(r[3]) : "r"(addr));
}
__device__ __forceinline__ void mma16816(float* c, const uint32_t* a, const uint32_t* b) {
    asm volatile("mma.sync.aligned.m16n8k16.row.col.f32.f16.f16.f32 "
        "{%0,%1,%2,%3}, {%4,%5,%6,%7}, {%8,%9}, {%0,%1,%2,%3};"
        : "+f"(c[0]), "+f"(c[1]), "+f"(c[2]), "+f"(c[3])
        : "r"(a[0]), "r"(a[1]), "r"(a[2]), "r"(a[3]), "r"(b[0]), "r"(b[1]));
}
#define CP16(dst, src) \
    asm volatile("cp.async.cg.shared.global [%0], [%1], 16;" :: "r"(dst), "l"(src) : "memory")
#define CPCOMMIT() asm volatile("cp.async.commit_group;" ::: "memory")
#define CPWAIT(n)  asm volatile("cp.async.wait_group %0;" :: "n"(n) : "memory")

#define CPA(WH, WL, KDIM, s, buf, STAGE) do { \
    _Pragma("unroll") for (int i = 0; i < 4; i++) { \
        int id = tid + i*256, term = id >> 9, rem = id & 511, row = rem >> 2, c = rem & 3; \
        const __half* src = (term ? (WL) : (WH)) + row*(KDIM) + (s)*32 + c*8; \
        uint32_t dst = sb + (buf)*(STAGE) + term*ATERM + row*RSTRIDE + c*16; \
        CP16(dst, src); } \
    CPCOMMIT(); } while (0)

// ---------------- fused setup ----------------
#define SU_W 576
#define SU_P 4704
#define SU_M 49
#define SU_I 21
__global__ void k_setup(const float4* __restrict__ inp,
                        const float* __restrict__ w1, const float* __restrict__ w2,
                        WinTab tab) {
    int b = blockIdx.x, tid = threadIdx.x;
    if (b < SU_W) {
        int t = b*256 + tid;
        if (t < 128) { g_sum1[t] = 0.f; g_sq1[t] = 0.f; g_sum2[t] = 0.f; g_sq2[t] = 0.f; }
        if (t < 128*160) {
            int oc = t / 160, k = t - oc*160;
            float v = (k < 147) ? w1[oc*147 + k] : 0.f;
            __half h = __float2half_rn(v);
            g_w1h[t] = h;
            g_w1l[t] = __float2half_rn(v - __half2float(h));
        }
        if (t < 128*1152) g_w2h[t] = __float2half_rn(w2[t]);
    } else if (b < SU_W + SU_P) {
        int i = (b - SU_W)*256 + tid;
        float4 v = inp[i];
        __half2 a = __floats2half2_rn(v.x, v.y);
        __half2 c = __floats2half2_rn(v.z, v.w);
        *(uint2*)(g_in16 + i*4) = make_uint2(*(uint32_t*)&a, *(uint32_t*)&c);
    } else if (b < SU_W + SU_P + SU_M) {
        int pix = (b - SU_W - SU_P)*256 + tid;
        int y = pix / 112, x = pix - y*112;
        int bi = y >> 3, bj = x >> 3;
        int sS = min(min(bi, bj), min(13 - bi, 13 - bj));
        int b2 = 8 * (sS + 1), c2v = 112 - b2;
        int w = (y < b2 && x < c2v) ? 0 : (x < b2 ? 1 : (y >= c2v ? 2 : 3));
        Win W = tab.w[sS*4 + w];
        int fy = ((y - W.to) * W.fh) / W.oh;
        int fx = ((x - W.lo) * W.fw) / W.ow;
        g_map16[pix] = (unsigned short)(W.base + fy * W.fw + fx);
    } else {
        int id = (b - SU_W - SU_P - SU_M)*256 + tid;
        int si = 0;
        #pragma unroll
        for (int i = 1; i < 28; i++) if (id >= tab.w[i].base) si = i;
        Win W = tab.w[si];
        int off = id - W.base;
        if (off < W.fh * W.fw) {
            int fy = off / W.fw, fx = off - fy*W.fw;
            int cy = ((fy+1)*W.oh + W.fh - 1)/W.fh - (fy*W.oh + W.fh - 1)/W.fh;
            int cx = ((fx+1)*W.ow + W.fw - 1)/W.fw - (fx*W.ow + W.fw - 1)/W.fw;
            g_wgt[id] = cy * cx;
            g_pc[id] = make_int2(W.ti + 2*fy - 3, W.li + 2*fx - 3);
        } else {
            g_wgt[id] = 0;
            g_pc[id] = make_int2(0, 0);
        }
    }
}

// ---------------- conv1: fp16x2 over packed pixels, fp16 gather ----------------
__global__ void __launch_bounds__(256, 3) k_conv1m() {
    extern __shared__ __align__(128) char dsm[];
    __shared__ int t_c[160];
    __shared__ signed char t_ky[160], t_kx[160];
    __shared__ float s_red[256];
    __shared__ float s_wgt[64];

    int tid = threadIdx.x, lane = tid & 31, wid = tid >> 5;
    int warp_m = wid & 3, warp_n = wid >> 2;

    if (tid < 160) {
        int k = tid;
        if (k < 147) {
            int c = k / 49, r = k - c*49, ky = r / 7, kx = r - ky*7;
            t_c[k] = c * 50176; t_ky[k] = (signed char)ky; t_kx[k] = (signed char)kx;
        } else { t_c[k] = -1; t_ky[k] = 0; t_kx[k] = 0; }
    }
    s_red[tid] = 0.f;

    int img = blockIdx.y;
    int pixbase = blockIdx.x * 64;
    if (tid < 64) s_wgt[tid] = (float)g_wgt[pixbase + tid];
    __syncthreads();

    int pix = pixbase + (tid >> 2);
    int kq = tid & 3;
    int2 pcv = g_pc[pix];
    int iy0 = pcv.x, ix0 = pcv.y;
    const __half* ibase = g_in16 + img * 150528;

    uint32_t sb = smem_u32(dsm);
    uint32_t Aln = (lane & 15)*RSTRIDE + (lane >> 4)*16;
    uint32_t Bln = ((lane >> 4)*8 + (lane & 7))*RSTRIDE + ((lane >> 3) & 1)*16;
    uint32_t bsts = (tid >> 2)*RSTRIDE + kq*16;

    uint32_t hw[4];
    #define C1_LDGB(s) do { int kb = (s)*32 + kq*8; \
        unsigned short bu[8]; \
        _Pragma("unroll") for (int j = 0; j < 8; j++) { \
            int k = kb + j; \
            int iy = iy0 + t_ky[k], ix = ix0 + t_kx[k]; \
            bool v = (t_c[k] >= 0) && ((unsigned)iy < 224u) && ((unsigned)ix < 224u); \
            bu[j] = v ? __half_as_ushort(__ldg(ibase + t_c[k] + iy*224 + ix)) : (unsigned short)0; } \
        _Pragma("unroll") for (int j = 0; j < 4; j++) \
            hw[j] = (uint32_t)bu[2*j] | ((uint32_t)bu[2*j+1] << 16); } while (0)
    #define C1_STSB(buf) do { \
        *(uint4*)(dsm + (buf)*STAGE1 + BOFF + bsts) = make_uint4(hw[0], hw[1], hw[2], hw[3]); } while (0)

    float acc[2][4][4];
    #pragma unroll
    for (int a = 0; a < 2; a++)
        #pragma unroll
        for (int b = 0; b < 4; b++)
            #pragma unroll
            for (int c = 0; c < 4; c++) acc[a][b][c] = 0.f;

    CPA(g_w1h, g_w1l, 160, 0, 0, STAGE1);
    CPA(g_w1h, g_w1l, 160, 1, 1, STAGE1);
    C1_LDGB(0);
    CPWAIT(1);
    C1_STSB(0);
    __syncthreads();

    for (int s = 0; s < 5; s++) {
        int buf = s & 1;
        if (s < 4) C1_LDGB(s + 1);
        {
            uint32_t Ab = sb + buf*STAGE1 + warp_m*(32*RSTRIDE);
            uint32_t Bb = sb + buf*STAGE1 + BOFF + warp_n*(32*RSTRIDE);
            #pragma unroll
            for (int h = 0; h < 2; h++) {
                uint32_t ab = Ab + h*32 + Aln;
                uint32_t bb = Bb + h*32 + Bln;
                uint32_t am[2][4], bq[4][2], t[4];
                ldsm4(bb, t); bq[0][0]=t[0]; bq[0][1]=t[1]; bq[1][0]=t[2]; bq[1][1]=t[3];
                ldsm4(bb + 16*RSTRIDE, t); bq[2][0]=t[0]; bq[2][1]=t[1]; bq[3][0]=t[2]; bq[3][1]=t[3];
                ldsm4(ab, am[0]); ldsm4(ab + 16*RSTRIDE, am[1]);
                #pragma unroll
                for (int mt = 0; mt < 2; mt++)
                    #pragma unroll
                    for (int nt = 0; nt < 4; nt++) mma16816(acc[mt][nt], am[mt], bq[nt]);
                ldsm4(ab + ATERM, am[0]); ldsm4(ab + ATERM + 16*RSTRIDE, am[1]);
                #pragma unroll
                for (int mt = 0; mt < 2; mt++)
                    #pragma unroll
                    for (int nt = 0; nt < 4; nt++) mma16816(acc[mt][nt], am[mt], bq[nt]);
            }
        }
        if (s < 4) {
            CPWAIT(0);
            C1_STSB(buf ^ 1);
            __syncthreads();
            if (s + 2 < 5) CPA(g_w1h, g_w1l, 160, s + 2, buf, STAGE1);
        }
    }

    int g = lane >> 2, cp = (lane & 3) * 2;
    #pragma unroll
    for (int mt = 0; mt < 2; mt++) {
        #pragma unroll
        for (int hh = 0; hh < 2; hh++) {
            int oc = warp_m*32 + mt*16 + hh*8 + g;
            float sv = 0.f, qv = 0.f;
            __half* obase = g_fpk + (size_t)(img*128 + oc)*NPMAX + pixbase;
            #pragma unroll
            for (int nt = 0; nt < 4; nt++) {
                float c0 = acc[mt][nt][hh*2], c1 = acc[mt][nt][hh*2 + 1];
                int pxl = warp_n*32 + nt*8 + cp;
                *(__half2*)(obase + pxl) = __floats2half2_rn(c0, c1);
                float w0 = s_wgt[pxl], w1 = s_wgt[pxl + 1];
                sv += w0*c0 + w1*c1; qv += w0*c0*c0 + w1*c1*c1;
            }
            atomicAdd(&s_red[oc], sv);
            atomicAdd(&s_red[128 + oc], qv);
        }
    }
    __syncthreads();
    if (tid < 128) {
        atomicAdd(&g_sum1[tid], s_red[tid]);
        atomicAdd(&g_sq1[tid],  s_red[128 + tid]);
    }
}

// ---------------- BN1 + ReLU + maxpool v4.1: warp-autonomous, y-unrolled x2 ----------------
__global__ void __launch_bounds__(256) k_pool(const float* __restrict__ gamma,
                                              const float* __restrict__ beta) {
    __shared__ __half s_val[4*NPMAX];

    int tid = threadIdx.x;
    int ncb0 = blockIdx.x * 4;

    {   // load 4 packed planes (43 KB)
        const uint4* src = (const uint4*)(g_fpk + (size_t)ncb0 * NPMAX);
        uint4* dst = (uint4*)s_val;
        #pragma unroll 11
        for (int i = tid; i < 4*NPMAX/8; i += 256) dst[i] = src[i];
    }
    __syncthreads();

    int w = tid >> 5, lane = tid & 31;
    int plane = w >> 1, wp = w & 1;
    int ncb = ncb0 + plane;
    int c = ncb & 127;
    float mean = g_sum1[c] * (1.f / N1F);
    float var  = g_sq1[c]  * (1.f / N1F) - mean * mean;
    float a = __ldg(gamma + c) * rsqrtf(var + 1e-5f);
    float bb = __ldg(beta + c) - a * mean;
    bool pos = (a >= 0.f);
    const __half* sp = s_val + plane * NPMAX;

    int x = 28*wp + lane;
    bool bnd = lane >= 28;
    int ce = max(56*wp - 1, 0);
    int c0 = bnd ? (ce & ~1) : 2*x;

    const __half NEGI = __ushort_as_half((unsigned short)0xFC00);
    const __half POSI = __ushort_as_half((unsigned short)0x7C00);
    __half cvx0 = NEGI, cvn0 = POSI, cvx1 = NEGI, cvn1 = POSI;

    __half* hpO = g_hp + GUARD + (size_t)ncb * PPLANE;
    __half* hsO = g_hs + GUARD + (size_t)ncb * PPLANE;
    __half* hmO = g_hm + GUARD + (size_t)ncb * PPLANE;

    int srcl = lane ? lane - 1 : 28;

    #pragma unroll 2
    for (int y = 0; y < 56; y += 2) {
        // hoisted loads for both sub-iterations (independent addresses -> MLP)
        const unsigned short* m0 = g_map16 + (2*y)*112;
        uint32_t u0 = __ldg((const uint32_t*)(m0 + c0));
        uint32_t u1 = __ldg((const uint32_t*)(m0 + 112 + c0));
        uint32_t u2 = __ldg((const uint32_t*)(m0 + 224 + c0));
        uint32_t u3 = __ldg((const uint32_t*)(m0 + 336 + c0));
        __half a0 = sp[u0 & 0xffff], a1 = sp[u0 >> 16];
        __half b0 = sp[u1 & 0xffff], b1 = sp[u1 >> 16];
        __half d0 = sp[u2 & 0xffff], d1 = sp[u2 >> 16];
        __half e0 = sp[u3 & 0xffff], e1 = sp[u3 >> 16];

        // ---- sub-iteration y ----
        {
            __half mx0 = __hmax(__hmax(cvx0, a0), b0);
            __half mn0 = __hmin(__hmin(cvn0, a0), b0);
            __half mx1 = __hmax(__hmax(cvx1, a1), b1);
            __half mn1 = __hmin(__hmin(cvn1, a1), b1);
            cvx0 = b0; cvn0 = b0; cvx1 = b1; cvn1 = b1;

            __half sx = mx1, sn = mn1;
            if (bnd && !(ce & 1)) { sx = mx0; sn = mn0; }
            uint32_t pk = ((uint32_t)__half_as_ushort(sx)) | ((uint32_t)__half_as_ushort(sn) << 16);
            uint32_t pv = __shfl_sync(0xFFFFFFFFu, pk, srcl);

            if (lane < 28) {
                float m;
                if (pos) {
                    __half px = __ushort_as_half((unsigned short)pv);
                    m = fmaf(a, __half2float(__hmax(__hmax(px, mx0), mx1)), bb);
                } else {
                    __half pn = __ushort_as_half((unsigned short)(pv >> 16));
                    m = fmaf(a, __half2float(__hmin(__hmin(pn, mn0), mn1)), bb);
                }
                __half h = __float2half_rn(fmaxf(m, 0.f));
                int p = (y + 1)*64 + x;
                hpO[p] = h; hsO[p - 1] = h; hmO[p + 1] = h;
            }
        }
        // ---- sub-iteration y+1 ----
        {
            __half mx0 = __hmax(__hmax(cvx0, d0), e0);
            __half mn0 = __hmin(__hmin(cvn0, d0), e0);
            __half mx1 = __hmax(__hmax(cvx1, d1), e1);
            __half mn1 = __hmin(__hmin(cvn1, d1), e1);
            cvx0 = e0; cvn0 = e0; cvx1 = e1; cvn1 = e1;

            __half sx = mx1, sn = mn1;
            if (bnd && !(ce & 1)) { sx = mx0; sn = mn0; }
            uint32_t pk = ((uint32_t)__half_as_ushort(sx)) | ((uint32_t)__half_as_ushort(sn) << 16);
            uint32_t pv = __shfl_sync(0xFFFFFFFFu, pk, srcl);

            if (lane < 28) {
                float m;
                if (pos) {
                    __half px = __ushort_as_half((unsigned short)pv);
                    m = fmaf(a, __half2float(__hmax(__hmax(px, mx0), mx1)), bb);
                } else {
                    __half pn = __ushort_as_half((unsigned short)(pv >> 16));
                    m = fmaf(a, __half2float(__hmin(__hmin(pn, mn0), mn1)), bb);
                }
                __half h = __float2half_rn(fmaxf(m, 0.f));
                int p = (y + 2)*64 + x;
                hpO[p] = h; hsO[p - 1] = h; hmO[p + 1] = h;
            }
        }
    }
}

// ---------------- conv2: two-row CTA, single-term A, all-16B cp.async, 4 stages ----------------
__global__ void __launch_bounds__(256, 2) k_conv2m(float* __restrict__ out) {
    extern __shared__ __align__(128) char dsm[];
    __shared__ int t_bo[1152];
    __shared__ float s_red[256];

    int tid = threadIdx.x, lane = tid & 31, wid = tid >> 5;
    int warp_m = wid & 3, warp_n = wid >> 2;

    for (int k = tid; k < 1152; k += 256) {
        int ic = k / 9, r = k - ic*9;
        int dy = r/3 - 1, dx = r - (r/3)*3 - 1;
        t_bo[k] = ((ic*PPLANE + dy*64 + 64) << 2) | (dx + 1);
    }
    s_red[tid] = 0.f;
    __syncthreads();

    int img = blockIdx.x / 28;
    int t2  = blockIdx.x - img*28;
    int yp0 = 2*t2 + 1;
    size_t ibase = (size_t)img * 128 * PPLANE;
    const __half* HP = g_hp + GUARD;
    const __half* HS = g_hs + GUARD;
    const __half* HM = g_hm + GUARD;

    uint32_t sb = smem_u32(dsm);

    #define C2_CPA(s, buf) do { \
        _Pragma("unroll") for (int i = 0; i < 2; i++) { \
            int id = tid + i*256, row = id >> 2, c = id & 3; \
            const __half* src = g_w2h + row*1152 + (s)*32 + c*8; \
            uint32_t dst = sb + (buf)*C2_STAGE + row*64 + (((c ^ ((row>>1)&3)) << 4)); \
            CP16(dst, src); } } while (0)
    #define C2_CPB(s, buf) do { \
        _Pragma("unroll") for (int i = 0; i < 2; i++) { \
            int id = tid + i*256, krow = id >> 4, G = id & 15; \
            int p = t_bo[(s)*32 + krow]; \
            int sel = p & 3; \
            const __half* base = (sel == 0) ? HM : ((sel == 1) ? HP : HS); \
            int r = G >> 3, gx = G & 7; \
            const __half* src = base + ibase + ((p >> 2) - 64) + (yp0 + r)*64 + gx*8; \
            uint32_t dst = sb + (buf)*C2_STAGE + C2_BOFF + krow*256 + (((G ^ (krow & 7)) << 4)); \
            CP16(dst, src); } } while (0)

    uint32_t arow = warp_m*32 + (lane & 15);
    uint32_t aswz = (arow >> 1) & 3;
    uint32_t arb  = arow * 64;
    uint32_t acol = lane >> 4;
    uint32_t brow = ((lane >> 3) & 1)*8 + (lane & 7);
    uint32_t bswz = lane & 7;
    uint32_t bg0  = warp_n*8 + (lane >> 4);

    float acc[2][8][4];
    #pragma unroll
    for (int a = 0; a < 2; a++)
        #pragma unroll
        for (int b = 0; b < 8; b++)
            #pragma unroll
            for (int c = 0; c < 4; c++) acc[a][b][c] = 0.f;

    C2_CPA(0, 0); C2_CPB(0, 0); CPCOMMIT();
    C2_CPA(1, 1); C2_CPB(1, 1); CPCOMMIT();
    C2_CPA(2, 2); C2_CPB(2, 2); CPCOMMIT();

    for (int s = 0; s < 36; s++) {
        CPWAIT(2);
        __syncthreads();
        int nb = (s + 3) & 3;
        if (s + 3 < 36) { C2_CPA(s + 3, nb); C2_CPB(s + 3, nb); }
        CPCOMMIT();

        uint32_t bufb = sb + (s & 3) * C2_STAGE;
        #pragma unroll
        for (int h = 0; h < 2; h++) {
            uint32_t t[4];
            uint32_t bq[8][2];
            uint32_t bbase = bufb + C2_BOFF + (h*16 + brow)*256;
            #pragma unroll
            for (int j = 0; j < 4; j++) {
                ldsm4t(bbase + (((bg0 + 2*j) ^ bswz) << 4), t);
                bq[2*j][0]   = t[0]; bq[2*j][1]   = t[1];
                bq[2*j+1][0] = t[2]; bq[2*j+1][1] = t[3];
            }
            uint32_t ac = (((h*2) + acol) ^ aswz) << 4;
            uint32_t am[2][4];
            ldsm4(bufb + arb + ac, am[0]);
            ldsm4(bufb + arb + 1024 + ac, am[1]);
            #pragma unroll
            for (int mt = 0; mt < 2; mt++)
                #pragma unroll
                for (int nt = 0; nt < 8; nt++) mma16816(acc[mt][nt], am[mt], bq[nt]);
        }
    }

    int g = lane >> 2, cp = (lane & 3) * 2;
    int yo = 2*t2 + warp_n;
    #pragma unroll
    for (int mt = 0; mt < 2; mt++) {
        #pragma unroll
        for (int hh = 0; hh < 2; hh++) {
            int oc = warp_m*32 + mt*16 + hh*8 + g;
            float sv = 0.f, qv = 0.f;
            float* obase = out + (size_t)(img*128 + oc)*NPIX2 + yo*56;
            #pragma unroll
            for (int nt = 0; nt < 8; nt++) {
                float c0 = acc[mt][nt][hh*2], c1 = acc[mt][nt][hh*2 + 1];
                int x = nt*8 + cp;
                if (x <= 55) { obase[x] = c0; sv += c0; qv += c0*c0; }
                if (x + 1 <= 55) { obase[x + 1] = c1; sv += c1; qv += c1*c1; }
            }
            atomicAdd(&s_red[oc], sv);
            atomicAdd(&s_red[128 + oc], qv);
        }
    }
    __syncthreads();
    if (tid < 128) {
        atomicAdd(&g_sum2[tid], s_red[tid]);
        atomicAdd(&g_sq2[tid],  s_red[128 + tid]);
    }
}

// ---------------- BN2 + ReLU in place (float4) ----------------
__global__ void k_bn2(float4* __restrict__ out,
                      const float* __restrict__ gamma, const float* __restrict__ beta) {
    int i = blockIdx.x * 256 + threadIdx.x;
    if (i >= BATCH * 128 * (NPIX2/4)) return;
    int c = (i / (NPIX2/4)) & 127;
    float mean = g_sum2[c] * (1.f / N2F);
    float var  = g_sq2[c]  * (1.f / N2F) - mean * mean;
    float a = __ldg(gamma + c) * rsqrtf(var + 1e-5f);
    float b = __ldg(beta + c) - a * mean;
    float4 v = out[i];
    v.x = fmaxf(fmaf(a, v.x, b), 0.f);
    v.y = fmaxf(fmaf(a, v.y, b), 0.f);
    v.z = fmaxf(fmaf(a, v.z, b), 0.f);
    v.w = fmaxf(fmaf(a, v.w, b), 0.f);
    out[i] = v;
}

// ---------------- launch ----------------
extern "C" void kernel_launch(void* const* d_in, const int* in_sizes, int n_in,
                              void* d_out, int out_size) {
    const float* inp = (const float*)d_in[0];
    const float* w1  = (const float*)d_in[1];
    const float* g1  = (const float*)d_in[2];
    const float* b1  = (const float*)d_in[3];
    const float* w2  = (const float*)d_in[4];
    const float* g2  = (const float*)d_in[5];
    const float* b2  = (const float*)d_in[6];
    float* out = (float*)d_out;

    WinTab tab;
    int np = 0;
    for (int s = 0; s < 7; s++) {
        int a = 16*s, b = a + 16, c = 224 - b, d = 224 - a;
        float scale = (float)(2.0 - (double)s / 6.0);
        for (int w = 0; w < 4; w++) {
            int t, l, bt, r;
            if      (w == 0) { t = a; l = a; bt = b; r = c; }
            else if (w == 1) { t = b; l = a; bt = d; r = b; }
            else if (w == 2) { t = c; l = b; bt = d; r = d; }
            else             { t = a; l = c; bt = c; r = d; }
            Win& W = tab.w[s*4 + w];
            W.ti = (int)((float)(t  + 6) / scale) - 3;
            W.li = (int)((float)(l  + 6) / scale) - 3;
            int bi = (int)((float)(bt + 6) / scale) + 3;
            int ri = (int)((float)(r  + 6) / scale) + 3;
            W.to = t >> 1; W.lo = l >> 1;
            W.oh = (bt >> 1) - W.to; W.ow = (r >> 1) - W.lo;
            W.fh = (bi - W.ti - 7) / 2 + 1;
            W.fw = (ri - W.li - 7) / 2 + 1;
            W.base = np;
            np += W.fh * W.fw;
        }
    }
    int tpi = (np + 63) / 64;

    cudaFuncSetAttribute(k_conv1m, cudaFuncAttributeMaxDynamicSharedMemorySize, DYN1);
    cudaFuncSetAttribute(k_conv2m, cudaFuncAttributeMaxDynamicSharedMemorySize, C2_DYN);

    k_setup<<<SU_W + SU_P + SU_M + SU_I, 256>>>((const float4*)inp, w1, w2, tab);
    k_conv1m<<<dim3(tpi, BATCH), 256, DYN1>>>();
    k_pool<<<BATCH*32, 256>>>(g1, b1);
    k_conv2m<<<BATCH*28, 256, C2_DYN>>>(out);
    k_bn2<<<(BATCH*128*(NPIX2/4) + 255) / 256, 256>>>((float4*)out, g2, b2);
}

// round 17
// speedup vs baseline: 1.1120x; 1.0751x over previous
#include <cuda_runtime.h>
#include <cuda_fp16.h>
#include <cstdint>

// ---------------- constants ----------------
#define IMG   224
#define BATCH 32
#define NPIX1 12544
#define NPIX2 3136
#define N1F   401408.0f
#define N2F   100352.0f

// conv1 smem geometry (single-term A + B)
#define RSTRIDE 80
#define BOFF1   10240          // A: 128 rows * 80B
#define STAGE1  15360          // + B: 64 rows * 80B
#define DYN1    30720

// conv2 geometry: two-row CTA, single-term A (8KB) + B (8KB), 4 stages
#define C2_BOFF  8192
#define C2_STAGE 16384
#define C2_DYN   (4*C2_STAGE)

// padded activation plane
#define PSTRIDE 64
#define PPLANE  3712
#define GUARD   128

// packed conv1 output
#define NPMAX 5376

struct Win { int ti, li, to, lo, oh, ow, fh, fw, base; };
struct WinTab { Win w[28]; };

// ---------------- scratch ----------------
__device__ __half g_in16[BATCH*3*IMG*IMG];
__device__ __half g_fpk[BATCH*128*NPMAX];
__device__ __half g_hp[GUARD + BATCH*128*PPLANE + GUARD];
__device__ __half g_hs[GUARD + BATCH*128*PPLANE + GUARD];
__device__ __half g_hm[GUARD + BATCH*128*PPLANE + GUARD];
__device__ __half g_w1h[128*160];
__device__ __half g_w2h[128*1152];
__device__ unsigned short g_map16[NPIX1];
__device__ int   g_wgt[NPMAX];
__device__ int2  g_pc[NPMAX];
__device__ float g_sum1[128], g_sq1[128], g_sum2[128], g_sq2[128];

// ---------------- helpers ----------------
__device__ __forceinline__ uint32_t smem_u32(const void* p) {
    uint32_t a;
    asm("{ .reg .u64 t; cvta.to.shared.u64 t, %1; cvt.u32.u64 %0, t; }" : "=r"(a) : "l"(p));
    return a;
}
__device__ __forceinline__ void ldsm4(uint32_t addr, uint32_t* r) {
    asm volatile("ldmatrix.sync.aligned.m8n8.x4.shared.b16 {%0,%1,%2,%3}, [%4];"
        : "=r"(r[0]), "=r"(r[1]), "=r"(r[2]), "=r"(r[3]) : "r"(addr));
}
__device__ __forceinline__ void ldsm4t(uint32_t addr, uint32_t* r) {
    asm volatile("ldmatrix.sync.aligned.m8n8.x4.trans.shared.b16 {%0,%1,%2,%3}, [%4];"
        : "=r"(r[0]), "=r"(r[1]), "=r"(r[2]), "=r"(r[3]) : "r"(addr));
}
__device__ __forceinline__ void mma16816(float* c, const uint32_t* a, const uint32_t* b) {
    asm volatile("mma.sync.aligned.m16n8k16.row.col.f32.f16.f16.f32 "
        "{%0,%1,%2,%3}, {%4,%5,%6,%7}, {%8,%9}, {%0,%1,%2,%3};"
        : "+f"(c[0]), "+f"(c[1]), "+f"(c[2]), "+f"(c[3])
        : "r"(a[0]), "r"(a[1]), "r"(a[2]), "r"(a[3]), "r"(b[0]), "r"(b[1]));
}
#define CP16(dst, src) \
    asm volatile("cp.async.cg.shared.global [%0], [%1], 16;" :: "r"(dst), "l"(src) : "memory")
#define CPCOMMIT() asm volatile("cp.async.commit_group;" ::: "memory")
#define CPWAIT(n)  asm volatile("cp.async.wait_group %0;" :: "n"(n) : "memory")

// conv1 A staging: 512 granules (single term), 2 per thread
#define CPA1(s, buf) do { \
    _Pragma("unroll") for (int i = 0; i < 2; i++) { \
        int id = tid + i*256, row = id >> 2, c = id & 3; \
        const __half* src = g_w1h + row*160 + (s)*32 + c*8; \
        uint32_t dst = sb + (buf)*STAGE1 + row*RSTRIDE + c*16; \
        CP16(dst, src); } \
    CPCOMMIT(); } while (0)

// ---------------- fused setup ----------------
#define SU_W 576
#define SU_P 4704
#define SU_M 49
#define SU_I 21
__global__ void k_setup(const float4* __restrict__ inp,
                        const float* __restrict__ w1, const float* __restrict__ w2,
                        WinTab tab) {
    int b = blockIdx.x, tid = threadIdx.x;
    if (b < SU_W) {
        int t = b*256 + tid;
        if (t < 128) { g_sum1[t] = 0.f; g_sq1[t] = 0.f; g_sum2[t] = 0.f; g_sq2[t] = 0.f; }
        if (t < 128*160) {
            int oc = t / 160, k = t - oc*160;
            float v = (k < 147) ? w1[oc*147 + k] : 0.f;
            g_w1h[t] = __float2half_rn(v);
        }
        if (t < 128*1152) g_w2h[t] = __float2half_rn(w2[t]);
    } else if (b < SU_W + SU_P) {
        int i = (b - SU_W)*256 + tid;
        float4 v = inp[i];
        __half2 a = __floats2half2_rn(v.x, v.y);
        __half2 c = __floats2half2_rn(v.z, v.w);
        *(uint2*)(g_in16 + i*4) = make_uint2(*(uint32_t*)&a, *(uint32_t*)&c);
    } else if (b < SU_W + SU_P + SU_M) {
        int pix = (b - SU_W - SU_P)*256 + tid;
        int y = pix / 112, x = pix - y*112;
        int bi = y >> 3, bj = x >> 3;
        int sS = min(min(bi, bj), min(13 - bi, 13 - bj));
        int b2 = 8 * (sS + 1), c2v = 112 - b2;
        int w = (y < b2 && x < c2v) ? 0 : (x < b2 ? 1 : (y >= c2v ? 2 : 3));
        Win W = tab.w[sS*4 + w];
        int fy = ((y - W.to) * W.fh) / W.oh;
        int fx = ((x - W.lo) * W.fw) / W.ow;
        g_map16[pix] = (unsigned short)(W.base + fy * W.fw + fx);
    } else {
        int id = (b - SU_W - SU_P - SU_M)*256 + tid;
        int si = 0;
        #pragma unroll
        for (int i = 1; i < 28; i++) if (id >= tab.w[i].base) si = i;
        Win W = tab.w[si];
        int off = id - W.base;
        if (off < W.fh * W.fw) {
            int fy = off / W.fw, fx = off - fy*W.fw;
            int cy = ((fy+1)*W.oh + W.fh - 1)/W.fh - (fy*W.oh + W.fh - 1)/W.fh;
            int cx = ((fx+1)*W.ow + W.fw - 1)/W.fw - (fx*W.ow + W.fw - 1)/W.fw;
            g_wgt[id] = cy * cx;
            g_pc[id] = make_int2(W.ti + 2*fy - 3, W.li + 2*fx - 3);
        } else {
            g_wgt[id] = 0;
            g_pc[id] = make_int2(0, 0);
        }
    }
}

// ---------------- conv1: single-term fp16 mma over packed pixels ----------------
__global__ void __launch_bounds__(256, 3) k_conv1m() {
    extern __shared__ __align__(128) char dsm[];
    __shared__ int t_c[160];
    __shared__ signed char t_ky[160], t_kx[160];
    __shared__ float s_red[256];
    __shared__ float s_wgt[64];

    int tid = threadIdx.x, lane = tid & 31, wid = tid >> 5;
    int warp_m = wid & 3, warp_n = wid >> 2;

    if (tid < 160) {
        int k = tid;
        if (k < 147) {
            int c = k / 49, r = k - c*49, ky = r / 7, kx = r - ky*7;
            t_c[k] = c * 50176; t_ky[k] = (signed char)ky; t_kx[k] = (signed char)kx;
        } else { t_c[k] = -1; t_ky[k] = 0; t_kx[k] = 0; }
    }
    s_red[tid] = 0.f;

    int img = blockIdx.y;
    int pixbase = blockIdx.x * 64;
    if (tid < 64) s_wgt[tid] = (float)g_wgt[pixbase + tid];
    __syncthreads();

    int pix = pixbase + (tid >> 2);
    int kq = tid & 3;
    int2 pcv = g_pc[pix];
    int iy0 = pcv.x, ix0 = pcv.y;
    const __half* ibase = g_in16 + img * 150528;

    uint32_t sb = smem_u32(dsm);
    uint32_t Aln = (lane & 15)*RSTRIDE + (lane >> 4)*16;
    uint32_t Bln = ((lane >> 4)*8 + (lane & 7))*RSTRIDE + ((lane >> 3) & 1)*16;
    uint32_t bsts = (tid >> 2)*RSTRIDE + kq*16;

    uint32_t hw[4];
    #define C1_LDGB(s) do { int kb = (s)*32 + kq*8; \
        unsigned short bu[8]; \
        _Pragma("unroll") for (int j = 0; j < 8; j++) { \
            int k = kb + j; \
            int iy = iy0 + t_ky[k], ix = ix0 + t_kx[k]; \
            bool v = (t_c[k] >= 0) && ((unsigned)iy < 224u) && ((unsigned)ix < 224u); \
            bu[j] = v ? __half_as_ushort(__ldg(ibase + t_c[k] + iy*224 + ix)) : (unsigned short)0; } \
        _Pragma("unroll") for (int j = 0; j < 4; j++) \
            hw[j] = (uint32_t)bu[2*j] | ((uint32_t)bu[2*j+1] << 16); } while (0)
    #define C1_STSB(buf) do { \
        *(uint4*)(dsm + (buf)*STAGE1 + BOFF1 + bsts) = make_uint4(hw[0], hw[1], hw[2], hw[3]); } while (0)

    float acc[2][4][4];
    #pragma unroll
    for (int a = 0; a < 2; a++)
        #pragma unroll
        for (int b = 0; b < 4; b++)
            #pragma unroll
            for (int c = 0; c < 4; c++) acc[a][b][c] = 0.f;

    CPA1(0, 0);
    CPA1(1, 1);
    C1_LDGB(0);
    CPWAIT(1);
    C1_STSB(0);
    __syncthreads();

    for (int s = 0; s < 5; s++) {
        int buf = s & 1;
        if (s < 4) C1_LDGB(s + 1);
        {
            uint32_t Ab = sb + buf*STAGE1 + warp_m*(32*RSTRIDE);
            uint32_t Bb = sb + buf*STAGE1 + BOFF1 + warp_n*(32*RSTRIDE);
            #pragma unroll
            for (int h = 0; h < 2; h++) {
                uint32_t ab = Ab + h*32 + Aln;
                uint32_t bb = Bb + h*32 + Bln;
                uint32_t am[2][4], bq[4][2], t[4];
                ldsm4(bb, t); bq[0][0]=t[0]; bq[0][1]=t[1]; bq[1][0]=t[2]; bq[1][1]=t[3];
                ldsm4(bb + 16*RSTRIDE, t); bq[2][0]=t[0]; bq[2][1]=t[1]; bq[3][0]=t[2]; bq[3][1]=t[3];
                ldsm4(ab, am[0]); ldsm4(ab + 16*RSTRIDE, am[1]);
                #pragma unroll
                for (int mt = 0; mt < 2; mt++)
                    #pragma unroll
                    for (int nt = 0; nt < 4; nt++) mma16816(acc[mt][nt], am[mt], bq[nt]);
            }
        }
        if (s < 4) {
            CPWAIT(0);
            C1_STSB(buf ^ 1);
            __syncthreads();
            if (s + 2 < 5) CPA1(s + 2, buf);
        }
    }

    int g = lane >> 2, cp = (lane & 3) * 2;
    #pragma unroll
    for (int mt = 0; mt < 2; mt++) {
        #pragma unroll
        for (int hh = 0; hh < 2; hh++) {
            int oc = warp_m*32 + mt*16 + hh*8 + g;
            float sv = 0.f, qv = 0.f;
            __half* obase = g_fpk + (size_t)(img*128 + oc)*NPMAX + pixbase;
            #pragma unroll
            for (int nt = 0; nt < 4; nt++) {
                float c0 = acc[mt][nt][hh*2], c1 = acc[mt][nt][hh*2 + 1];
                int pxl = warp_n*32 + nt*8 + cp;
                *(__half2*)(obase + pxl) = __floats2half2_rn(c0, c1);
                float w0 = s_wgt[pxl], w1 = s_wgt[pxl + 1];
                sv += w0*c0 + w1*c1; qv += w0*c0*c0 + w1*c1*c1;
            }
            atomicAdd(&s_red[oc], sv);
            atomicAdd(&s_red[128 + oc], qv);
        }
    }
    __syncthreads();
    if (tid < 128) {
        atomicAdd(&g_sum1[tid], s_red[tid]);
        atomicAdd(&g_sq1[tid],  s_red[128 + tid]);
    }
}

// ---------------- BN1 + ReLU + maxpool v4.1: warp-autonomous, y-unrolled x2 ----------------
__global__ void __launch_bounds__(256) k_pool(const float* __restrict__ gamma,
                                              const float* __restrict__ beta) {
    __shared__ __half s_val[4*NPMAX];

    int tid = threadIdx.x;
    int ncb0 = blockIdx.x * 4;

    {
        const uint4* src = (const uint4*)(g_fpk + (size_t)ncb0 * NPMAX);
        uint4* dst = (uint4*)s_val;
        #pragma unroll 11
        for (int i = tid; i < 4*NPMAX/8; i += 256) dst[i] = src[i];
    }
    __syncthreads();

    int w = tid >> 5, lane = tid & 31;
    int plane = w >> 1, wp = w & 1;
    int ncb = ncb0 + plane;
    int c = ncb & 127;
    float mean = g_sum1[c] * (1.f / N1F);
    float var  = g_sq1[c]  * (1.f / N1F) - mean * mean;
    float a = __ldg(gamma + c) * rsqrtf(var + 1e-5f);
    float bb = __ldg(beta + c) - a * mean;
    bool pos = (a >= 0.f);
    const __half* sp = s_val + plane * NPMAX;

    int x = 28*wp + lane;
    bool bnd = lane >= 28;
    int ce = max(56*wp - 1, 0);
    int c0 = bnd ? (ce & ~1) : 2*x;

    const __half NEGI = __ushort_as_half((unsigned short)0xFC00);
    const __half POSI = __ushort_as_half((unsigned short)0x7C00);
    __half cvx0 = NEGI, cvn0 = POSI, cvx1 = NEGI, cvn1 = POSI;

    __half* hpO = g_hp + GUARD + (size_t)ncb * PPLANE;
    __half* hsO = g_hs + GUARD + (size_t)ncb * PPLANE;
    __half* hmO = g_hm + GUARD + (size_t)ncb * PPLANE;

    int srcl = lane ? lane - 1 : 28;

    #pragma unroll 2
    for (int y = 0; y < 56; y += 2) {
        const unsigned short* m0 = g_map16 + (2*y)*112;
        uint32_t u0 = __ldg((const uint32_t*)(m0 + c0));
        uint32_t u1 = __ldg((const uint32_t*)(m0 + 112 + c0));
        uint32_t u2 = __ldg((const uint32_t*)(m0 + 224 + c0));
        uint32_t u3 = __ldg((const uint32_t*)(m0 + 336 + c0));
        __half a0 = sp[u0 & 0xffff], a1 = sp[u0 >> 16];
        __half b0 = sp[u1 & 0xffff], b1 = sp[u1 >> 16];
        __half d0 = sp[u2 & 0xffff], d1 = sp[u2 >> 16];
        __half e0 = sp[u3 & 0xffff], e1 = sp[u3 >> 16];

        {
            __half mx0 = __hmax(__hmax(cvx0, a0), b0);
            __half mn0 = __hmin(__hmin(cvn0, a0), b0);
            __half mx1 = __hmax(__hmax(cvx1, a1), b1);
            __half mn1 = __hmin(__hmin(cvn1, a1), b1);
            cvx0 = b0; cvn0 = b0; cvx1 = b1; cvn1 = b1;

            __half sx = mx1, sn = mn1;
            if (bnd && !(ce & 1)) { sx = mx0; sn = mn0; }
            uint32_t pk = ((uint32_t)__half_as_ushort(sx)) | ((uint32_t)__half_as_ushort(sn) << 16);
            uint32_t pv = __shfl_sync(0xFFFFFFFFu, pk, srcl);

            if (lane < 28) {
                float m;
                if (pos) {
                    __half px = __ushort_as_half((unsigned short)pv);
                    m = fmaf(a, __half2float(__hmax(__hmax(px, mx0), mx1)), bb);
                } else {
                    __half pn = __ushort_as_half((unsigned short)(pv >> 16));
                    m = fmaf(a, __half2float(__hmin(__hmin(pn, mn0), mn1)), bb);
                }
                __half h = __float2half_rn(fmaxf(m, 0.f));
                int p = (y + 1)*64 + x;
                hpO[p] = h; hsO[p - 1] = h; hmO[p + 1] = h;
            }
        }
        {
            __half mx0 = __hmax(__hmax(cvx0, d0), e0);
            __half mn0 = __hmin(__hmin(cvn0, d0), e0);
            __half mx1 = __hmax(__hmax(cvx1, d1), e1);
            __half mn1 = __hmin(__hmin(cvn1, d1), e1);
            cvx0 = e0; cvn0 = e0; cvx1 = e1; cvn1 = e1;

            __half sx = mx1, sn = mn1;
            if (bnd && !(ce & 1)) { sx = mx0; sn = mn0; }
            uint32_t pk = ((uint32_t)__half_as_ushort(sx)) | ((uint32_t)__half_as_ushort(sn) << 16);
            uint32_t pv = __shfl_sync(0xFFFFFFFFu, pk, srcl);

            if (lane < 28) {
                float m;
                if (pos) {
                    __half px = __ushort_as_half((unsigned short)pv);
                    m = fmaf(a, __half2float(__hmax(__hmax(px, mx0), mx1)), bb);
                } else {
                    __half pn = __ushort_as_half((unsigned short)(pv >> 16));
                    m = fmaf(a, __half2float(__hmin(__hmin(pn, mn0), mn1)), bb);
                }
                __half h = __float2half_rn(fmaxf(m, 0.f));
                int p = (y + 2)*64 + x;
                hpO[p] = h; hsO[p - 1] = h; hmO[p + 1] = h;
            }
        }
    }
}

// ---------------- conv2: two-row CTA, single-term A, all-16B cp.async, 4 stages ----------------
__global__ void __launch_bounds__(256, 2) k_conv2m(float* __restrict__ out) {
    extern __shared__ __align__(128) char dsm[];
    __shared__ int t_bo[1152];
    __shared__ float s_red[256];

    int tid = threadIdx.x, lane = tid & 31, wid = tid >> 5;
    int warp_m = wid & 3, warp_n = wid >> 2;

    for (int k = tid; k < 1152; k += 256) {
        int ic = k / 9, r = k - ic*9;
        int dy = r/3 - 1, dx = r - (r/3)*3 - 1;
        t_bo[k] = ((ic*PPLANE + dy*64 + 64) << 2) | (dx + 1);
    }
    s_red[tid] = 0.f;
    __syncthreads();

    int img = blockIdx.x / 28;
    int t2  = blockIdx.x - img*28;
    int yp0 = 2*t2 + 1;
    size_t ibase = (size_t)img * 128 * PPLANE;
    const __half* HP = g_hp + GUARD;
    const __half* HS = g_hs + GUARD;
    const __half* HM = g_hm + GUARD;

    uint32_t sb = smem_u32(dsm);

    #define C2_CPA(s, buf) do { \
        _Pragma("unroll") for (int i = 0; i < 2; i++) { \
            int id = tid + i*256, row = id >> 2, c = id & 3; \
            const __half* src = g_w2h + row*1152 + (s)*32 + c*8; \
            uint32_t dst = sb + (buf)*C2_STAGE + row*64 + (((c ^ ((row>>1)&3)) << 4)); \
            CP16(dst, src); } } while (0)
    #define C2_CPB(s, buf) do { \
        _Pragma("unroll") for (int i = 0; i < 2; i++) { \
            int id = tid + i*256, krow = id >> 4, G = id & 15; \
            int p = t_bo[(s)*32 + krow]; \
            int sel = p & 3; \
            const __half* base = (sel == 0) ? HM : ((sel == 1) ? HP : HS); \
            int r = G >> 3, gx = G & 7; \
            const __half* src = base + ibase + ((p >> 2) - 64) + (yp0 + r)*64 + gx*8; \
            uint32_t dst = sb + (buf)*C2_STAGE + C2_BOFF + krow*256 + (((G ^ (krow & 7)) << 4)); \
            CP16(dst, src); } } while (0)

    uint32_t arow = warp_m*32 + (lane & 15);
    uint32_t aswz = (arow >> 1) & 3;
    uint32_t arb  = arow * 64;
    uint32_t acol = lane >> 4;
    uint32_t brow = ((lane >> 3) & 1)*8 + (lane & 7);
    uint32_t bswz = lane & 7;
    uint32_t bg0  = warp_n*8 + (lane >> 4);

    float acc[2][8][4];
    #pragma unroll
    for (int a = 0; a < 2; a++)
        #pragma unroll
        for (int b = 0; b < 8; b++)
            #pragma unroll
            for (int c = 0; c < 4; c++) acc[a][b][c] = 0.f;

    C2_CPA(0, 0); C2_CPB(0, 0); CPCOMMIT();
    C2_CPA(1, 1); C2_CPB(1, 1); CPCOMMIT();
    C2_CPA(2, 2); C2_CPB(2, 2); CPCOMMIT();

    for (int s = 0; s < 36; s++) {
        CPWAIT(2);
        __syncthreads();
        int nb = (s + 3) & 3;
        if (s + 3 < 36) { C2_CPA(s + 3, nb); C2_CPB(s + 3, nb); }
        CPCOMMIT();

        uint32_t bufb = sb + (s & 3) * C2_STAGE;
        #pragma unroll
        for (int h = 0; h < 2; h++) {
            uint32_t t[4];
            uint32_t bq[8][2];
            uint32_t bbase = bufb + C2_BOFF + (h*16 + brow)*256;
            #pragma unroll
            for (int j = 0; j < 4; j++) {
                ldsm4t(bbase + (((bg0 + 2*j) ^ bswz) << 4), t);
                bq[2*j][0]   = t[0]; bq[2*j][1]   = t[1];
                bq[2*j+1][0] = t[2]; bq[2*j+1][1] = t[3];
            }
            uint32_t ac = (((h*2) + acol) ^ aswz) << 4;
            uint32_t am[2][4];
            ldsm4(bufb + arb + ac, am[0]);
            ldsm4(bufb + arb + 1024 + ac, am[1]);
            #pragma unroll
            for (int mt = 0; mt < 2; mt++)
                #pragma unroll
                for (int nt = 0; nt < 8; nt++) mma16816(acc[mt][nt], am[mt], bq[nt]);
        }
    }

    int g = lane >> 2, cp = (lane & 3) * 2;
    int yo = 2*t2 + warp_n;
    #pragma unroll
    for (int mt = 0; mt < 2; mt++) {
        #pragma unroll
        for (int hh = 0; hh < 2; hh++) {
            int oc = warp_m*32 + mt*16 + hh*8 + g;
            float sv = 0.f, qv = 0.f;
            float* obase = out + (size_t)(img*128 + oc)*NPIX2 + yo*56;
            #pragma unroll
            for (int nt = 0; nt < 8; nt++) {
                float c0 = acc[mt][nt][hh*2], c1 = acc[mt][nt][hh*2 + 1];
                int x = nt*8 + cp;
                if (x <= 55) { obase[x] = c0; sv += c0; qv += c0*c0; }
                if (x + 1 <= 55) { obase[x + 1] = c1; sv += c1; qv += c1*c1; }
            }
            atomicAdd(&s_red[oc], sv);
            atomicAdd(&s_red[128 + oc], qv);
        }
    }
    __syncthreads();
    if (tid < 128) {
        atomicAdd(&g_sum2[tid], s_red[tid]);
        atomicAdd(&g_sq2[tid],  s_red[128 + tid]);
    }
}

// ---------------- BN2 + ReLU in place (float4) ----------------
__global__ void k_bn2(float4* __restrict__ out,
                      const float* __restrict__ gamma, const float* __restrict__ beta) {
    int i = blockIdx.x * 256 + threadIdx.x;
    if (i >= BATCH * 128 * (NPIX2/4)) return;
    int c = (i / (NPIX2/4)) & 127;
    float mean = g_sum2[c] * (1.f / N2F);
    float var  = g_sq2[c]  * (1.f / N2F) - mean * mean;
    float a = __ldg(gamma + c) * rsqrtf(var + 1e-5f);
    float b = __ldg(beta + c) - a * mean;
    float4 v = out[i];
    v.x = fmaxf(fmaf(a, v.x, b), 0.f);
    v.y = fmaxf(fmaf(a, v.y, b), 0.f);
    v.z = fmaxf(fmaf(a, v.z, b), 0.f);
    v.w = fmaxf(fmaf(a, v.w, b), 0.f);
    out[i] = v;
}

// ---------------- launch ----------------
extern "C" void kernel_launch(void* const* d_in, const int* in_sizes, int n_in,
                              void* d_out, int out_size) {
    const float* inp = (const float*)d_in[0];
    const float* w1  = (const float*)d_in[1];
    const float* g1  = (const float*)d_in[2];
    const float* b1  = (const float*)d_in[3];
    const float* w2  = (const float*)d_in[4];
    const float* g2  = (const float*)d_in[5];
    const float* b2  = (const float*)d_in[6];
    float* out = (float*)d_out;

    WinTab tab;
    int np = 0;
    for (int s = 0; s < 7; s++) {
        int a = 16*s, b = a + 16, c = 224 - b, d = 224 - a;
        float scale = (float)(2.0 - (double)s / 6.0);
        for (int w = 0; w < 4; w++) {
            int t, l, bt, r;
            if      (w == 0) { t = a; l = a; bt = b; r = c; }
            else if (w == 1) { t = b; l = a; bt = d; r = b; }
            else if (w == 2) { t = c; l = b; bt = d; r = d; }
            else             { t = a; l = c; bt = c; r = d; }
            Win& W = tab.w[s*4 + w];
            W.ti = (int)((float)(t  + 6) / scale) - 3;
            W.li = (int)((float)(l  + 6) / scale) - 3;
            int bi = (int)((float)(bt + 6) / scale) + 3;
            int ri = (int)((float)(r  + 6) / scale) + 3;
            W.to = t >> 1; W.lo = l >> 1;
            W.oh = (bt >> 1) - W.to; W.ow = (r >> 1) - W.lo;
            W.fh = (bi - W.ti - 7) / 2 + 1;
            W.fw = (ri - W.li - 7) / 2 + 1;
            W.base = np;
            np += W.fh * W.fw;
        }
    }
    int tpi = (np + 63) / 64;

    cudaFuncSetAttribute(k_conv1m, cudaFuncAttributeMaxDynamicSharedMemorySize, DYN1);
    cudaFuncSetAttribute(k_conv2m, cudaFuncAttributeMaxDynamicSharedMemorySize, C2_DYN);

    k_setup<<<SU_W + SU_P + SU_M + SU_I, 256>>>((const float4*)inp, w1, w2, tab);
    k_conv1m<<<dim3(tpi, BATCH), 256, DYN1>>>();
    k_pool<<<BATCH*32, 256>>>(g1, b1);
    k_conv2m<<<BATCH*28, 256, C2_DYN>>>(out);
    k_bn2<<<(BATCH*128*(NPIX2/4) + 255) / 256, 256>>>((float4*)out, g2, b2);
}